// round 5
// baseline (speedup 1.0000x reference)
#include <cuda_runtime.h>
#include <math.h>

#define NSAMP  24000
#define NV4    6000          // NSAMP / 4
#define CH     8             // samples per thread-chunk
#define NCHUNK 3000          // 24000 / 8
#define CUTOFF 0.1f
#define OMC    0.9f          // 1 - CUTOFF
#define A8     0.43046721f   // 0.9^8
#define TSTEP  (1.0f / 23999.0f)

// Global scratch (device globals: no allocation)
__device__ float4 g_trans4[NV4];
__device__ float4 g_res4[NV4];

__device__ __forceinline__ float tanh_fast(float x) {
    // exact identity tanh(x) = 1 - 2/(e^{2x}+1); saturates correctly at +-inf
    float e = __expf(2.0f * x);
    return 1.0f - __fdividef(2.0f, e + 1.0f);
}

// ======================= Kernel 1: transient (multi-SM) =======================
// Each warp owns 32 chunks of 8 samples (256 samples). Its filter carry-in is
// computed redundantly from the PREVIOUS warp's 256 samples starting at y=0
// (halo truncation error ~0.9^256 ~ 2e-12, far below fp32 noise).
__global__ __launch_bounds__(128)
void k_transient(const float* __restrict__ p, const float* __restrict__ noise_t)
{
    const int lane  = threadIdx.x & 31;
    const int wgid  = (blockIdx.x * blockDim.x + threadIdx.x) >> 5;  // global warp
    const int wch0  = wgid * 32;                                     // first chunk

    const float decay_t = p[1];
    const float freq_t  = p[2];
    const float sat     = p[3];
    const float gain_t  = p[4];

    const float4* ntv = (const float4*)noise_t;

    // ---- halo: reduce previous warp's chunk (lane -> chunk wch0-32+lane) ----
    float a = 1.0f, b = 0.0f;
    {
        int hc = wch0 - 32 + lane;
        if (hc >= 0 && hc < NCHUNK) {
            float4 x0 = ntv[hc * 2];
            float4 x1 = ntv[hc * 2 + 1];
            float y;
            y = CUTOFF * x0.x;
            y = fmaf(OMC, y, CUTOFF * x0.y);
            y = fmaf(OMC, y, CUTOFF * x0.z);
            y = fmaf(OMC, y, CUTOFF * x0.w);
            y = fmaf(OMC, y, CUTOFF * x1.x);
            y = fmaf(OMC, y, CUTOFF * x1.y);
            y = fmaf(OMC, y, CUTOFF * x1.z);
            y = fmaf(OMC, y, CUTOFF * x1.w);
            b = y; a = A8;
        }
    }
    // inclusive affine scan; lane 31's b = filter state entering this warp
    #pragma unroll
    for (int off = 1; off < 32; off <<= 1) {
        float au = __shfl_up_sync(0xffffffffu, a, off);
        float bu = __shfl_up_sync(0xffffffffu, b, off);
        if (lane >= off) { b = fmaf(a, bu, b); a *= au; }
    }
    const float y_warp = __shfl_sync(0xffffffffu, b, 31);

    // ---- main chunk: partials from y=0 (kept in registers) ----
    const int  mc  = wch0 + lane;
    const bool act = (mc < NCHUNK);
    float bk[CH];
    float a2 = 1.0f, b2 = 0.0f;
    if (act) {
        float4 x0 = ntv[mc * 2];
        float4 x1 = ntv[mc * 2 + 1];
        float xs[CH] = {x0.x, x0.y, x0.z, x0.w, x1.x, x1.y, x1.z, x1.w};
        float y = 0.0f;
        #pragma unroll
        for (int s = 0; s < CH; ++s) { y = fmaf(OMC, y, CUTOFF * xs[s]); bk[s] = y; }
        b2 = y; a2 = A8;
    }
    // exclusive affine scan -> carry-in for this chunk
    #pragma unroll
    for (int off = 1; off < 32; off <<= 1) {
        float au = __shfl_up_sync(0xffffffffu, a2, off);
        float bu = __shfl_up_sync(0xffffffffu, b2, off);
        if (lane >= off) { b2 = fmaf(a2, bu, b2); a2 *= au; }
    }
    float a_ie = __shfl_up_sync(0xffffffffu, a2, 1);
    float b_ie = __shfl_up_sync(0xffffffffu, b2, 1);
    if (lane == 0) { a_ie = 1.0f; b_ie = 0.0f; }
    const float y_in = fmaf(a_ie, y_warp, b_ie);

    // ---- transient: sine/exp recurrences over 8 samples ----
    if (act) {
        const float t0 = (float)(mc * CH) * TSTEP;
        const float w  = 6.2831853f * freq_t;
        float sn, cs;
        sincosf(w * t0, &sn, &cs);                 // accurate start phase
        const float sd = __sinf(w * TSTEP);        // tiny-arg step rotation
        const float cd = __cosf(w * TSTEP);
        float e1 = __expf(-decay_t * t0);
        float e2 = __expf(-20.0f * decay_t * t0);
        const float m1 = __expf(-decay_t * TSTEP);
        const float m2 = __expf(-20.0f * decay_t * TSTEP);
        const float g2  = gain_t * 0.5f;
        const float gts = gain_t * sat;
        float pk = OMC;                             // 0.9^(k+1)
        float tr[CH];
        #pragma unroll
        for (int s = 0; s < CH; ++s) {
            float y  = fmaf(pk, y_in, bk[s]);       // exact filter output
            float sq = tanh_fast(sn * e1 * gts);    // saturated sine
            tr[s] = fmaf(y * e2, g2, sq);           // + noise component
            float sn2 = fmaf(sn, cd,  cs * sd);
            float cs2 = fmaf(cs, cd, -sn * sd);
            sn = sn2; cs = cs2;
            e1 *= m1; e2 *= m2; pk *= OMC;
        }
        g_trans4[mc * 2]     = make_float4(tr[0], tr[1], tr[2], tr[3]);
        g_trans4[mc * 2 + 1] = make_float4(tr[4], tr[5], tr[6], tr[7]);
    }
}

// ======================= Kernel 2: resonator (1 CTA) =======================
__global__ __launch_bounds__(1024)
void k_resonator(const float* __restrict__ p)
{
    const float* trans = (const float*)g_trans4;
    float*       res   = (float*)g_res4;
    const int tid = threadIdx.x;

    const float feedback = p[6];
    const float D  = 48000.0f / p[5];
    const int   Di = (int)D;
    const bool fastp = (D >= 1.0f) && ((float)Di == D) && (Di <= 1024);

    if (fastp) {
        // Integer delay: frac == 0 exactly -> Di independent register chains.
        // Coalesced global traffic (L2-resident after kernel 1).
        if (tid < Di) {
            float yv = trans[tid];        // i < D => valid==0 => out = transient
            res[tid] = yv;
            #pragma unroll 4
            for (int i = tid + Di; i < NSAMP; i += Di) {
                yv = fmaf(feedback, yv, trans[i]);
                res[i] = yv;
            }
        }
    } else {
        // Generic fractional delay: stage in smem, wave-synchronous.
        extern __shared__ float sm[];
        float* str = sm;             // trans copy
        float* sre = sm + NSAMP;     // resonator output (zero-init, as reference)
        for (int i = tid; i < NSAMP; i += 1024) { str[i] = trans[i]; sre[i] = 0.0f; }
        __syncthreads();
        if (tid == 0) sre[0] = str[0];
        int cD = (int)ceilf(D);
        int W  = min(max(cD - 1, 1), 1024);
        __syncthreads();
        for (int s0 = 1; s0 < NSAMP; s0 += W) {
            const int i = s0 + tid;
            if (tid < W && i < NSAMP) {
                float delayed = (float)i - D;
                float valid   = (delayed >= 0.0f) ? 1.0f : 0.0f;
                int fl = min(max((int)floorf(delayed), 0), NSAMP - 1);
                int ce = min(fl + 1, NSAMP - 1);
                float frac = delayed - (float)fl;    // after clamp, as in reference
                float interp = (1.0f - frac) * sre[fl] + frac * sre[ce];
                sre[i] = str[i] + feedback * interp * valid;
            }
            __syncthreads();
        }
        for (int i = tid; i < NSAMP; i += 1024) res[i] = sre[i];
    }
}

// ======================= Kernel 3: noise env + final sum =======================
__global__ __launch_bounds__(128)
void k_final(const float* __restrict__ p, const float* __restrict__ noise_n,
             float* __restrict__ out)
{
    const int i4 = blockIdx.x * blockDim.x + threadIdx.x;
    if (i4 >= NV4) return;

    const float gain_r   = p[7];
    const float attack_n = p[8];
    const float decay_n  = p[9];
    const float gain_n   = p[10];

    const float t0 = (float)(4 * i4) * TSTEP;
    const float eA = __expf(-attack_n * t0);
    const float eD = __expf(-decay_n  * t0);
    const float a1 = __expf(-attack_n * TSTEP);
    const float d1 = __expf(-decay_n  * TSTEP);
    const float a2 = a1 * a1, a3 = a2 * a1;
    const float d2 = d1 * d1, d3 = d2 * d1;

    float4 nn = ((const float4*)noise_n)[i4];
    float4 tr = g_trans4[i4];
    float4 rs = g_res4[i4];

    float e0v = (1.0f - eA)      *  eD;
    float e1v = (1.0f - eA * a1) * (eD * d1);
    float e2v = (1.0f - eA * a2) * (eD * d2);
    float e3v = (1.0f - eA * a3) * (eD * d3);

    float4 o;
    o.x = fmaf(nn.x * gain_n, e0v, fmaf(rs.x, gain_r, tr.x));
    o.y = fmaf(nn.y * gain_n, e1v, fmaf(rs.y, gain_r, tr.y));
    o.z = fmaf(nn.z * gain_n, e2v, fmaf(rs.z, gain_r, tr.z));
    o.w = fmaf(nn.w * gain_n, e3v, fmaf(rs.w, gain_r, tr.w));
    ((float4*)out)[i4] = o;
}

extern "C" void kernel_launch(void* const* d_in, const int* in_sizes, int n_in,
                              void* d_out, int out_size)
{
    const float* params  = (const float*)d_in[0];
    const float* noise_t = (const float*)d_in[1];
    const float* noise_n = (const float*)d_in[2];
    float* out = (float*)d_out;

    const size_t smem_res = 2u * NSAMP * sizeof(float);   // 192000 B (generic path)
    cudaFuncSetAttribute(k_resonator,
                         cudaFuncAttributeMaxDynamicSharedMemorySize,
                         (int)smem_res);

    // 24 CTAs x 128 thr = 96 warps x 32 chunks = 3072 chunks >= 3000
    k_transient<<<24, 128>>>(params, noise_t);
    k_resonator<<<1, 1024, smem_res>>>(params);
    // 47 CTAs x 128 = 6016 >= 6000 float4s
    k_final<<<47, 128>>>(params, noise_n, out);
}

// round 6
// speedup vs baseline: 1.8246x; 1.8246x over previous
#include <cuda_runtime.h>
#include <math.h>

#define NSAMP  24000
#define CH     12            // samples per lane
#define SPW    384           // samples per warp (32 * 12)
#define NCTA   8             // cluster size = grid size
#define NTHR   256           // 8 warps per CTA -> 64 warps total
#define CUTOFF 0.1f
#define OMC    0.9f          // 1 - CUTOFF
#define A12    0.28242954f   // 0.9^12
#define TSTEP  (1.0f / 23999.0f)

// Global scratch (device globals: no allocation)
__device__ float g_trans[NSAMP];
__device__ float g_res[NSAMP];

__device__ __forceinline__ float tanh_fast(float x) {
    // exact identity tanh(x) = 1 - 2/(e^{2x}+1); saturates correctly at +-inf
    float e = __expf(2.0f * x);
    return 1.0f - __fdividef(2.0f, e + 1.0f);
}

__device__ __forceinline__ void cluster_sync() {
    asm volatile("barrier.cluster.arrive.aligned;" ::: "memory");
    asm volatile("barrier.cluster.wait.aligned;"   ::: "memory");
}

__device__ __forceinline__ float filt12(const float4 x0, const float4 x1,
                                        const float4 x2, float y) {
    y = fmaf(OMC, y, CUTOFF * x0.x);
    y = fmaf(OMC, y, CUTOFF * x0.y);
    y = fmaf(OMC, y, CUTOFF * x0.z);
    y = fmaf(OMC, y, CUTOFF * x0.w);
    y = fmaf(OMC, y, CUTOFF * x1.x);
    y = fmaf(OMC, y, CUTOFF * x1.y);
    y = fmaf(OMC, y, CUTOFF * x1.z);
    y = fmaf(OMC, y, CUTOFF * x1.w);
    y = fmaf(OMC, y, CUTOFF * x2.x);
    y = fmaf(OMC, y, CUTOFF * x2.y);
    y = fmaf(OMC, y, CUTOFF * x2.z);
    y = fmaf(OMC, y, CUTOFF * x2.w);
    return y;
}

__global__ __launch_bounds__(NTHR, 1) __cluster_dims__(NCTA, 1, 1)
void drum_synth_cluster(const float* __restrict__ p,
                        const float* __restrict__ noise_t,
                        const float* __restrict__ noise_n,
                        float* __restrict__ out)
{
    extern __shared__ float sm[];      // CTA0: str[24000] (+ sre[24000] generic path)
    const int tid  = threadIdx.x;
    const int lane = tid & 31;
    const int w    = blockIdx.x * (NTHR / 32) + (tid >> 5);   // global warp 0..63

    const float decay_t  = p[1];
    const float freq_t   = p[2];
    const float sat      = p[3];
    const float gain_t   = p[4];
    const float freq_r   = p[5];
    const float feedback = p[6];
    const float gain_r   = p[7];
    const float attack_n = p[8];
    const float decay_n  = p[9];
    const float gain_n   = p[10];

    const int  s0  = w * SPW + lane * CH;          // first sample of this lane
    const bool act = (s0 + CH <= NSAMP);
    const int  v0  = s0 >> 2;                       // float4 index (12 | 4*lane ok)
    const float4* ntv = (const float4*)noise_t;

    // ======== Phase A1: halo — redundantly reduce previous warp's 384 samples ====
    float ha = 1.0f, hb = 0.0f;
    {
        const int hs0 = s0 - SPW;
        if (hs0 >= 0 && hs0 + CH <= NSAMP) {
            const int hv = hs0 >> 2;
            hb = filt12(ntv[hv], ntv[hv + 1], ntv[hv + 2], 0.0f);
            ha = A12;
        }
    }
    #pragma unroll
    for (int off = 1; off < 32; off <<= 1) {
        float au = __shfl_up_sync(0xffffffffu, ha, off);
        float bu = __shfl_up_sync(0xffffffffu, hb, off);
        if (lane >= off) { hb = fmaf(ha, bu, hb); ha *= au; }
    }
    const float y_warp = __shfl_sync(0xffffffffu, hb, 31);   // filter state at warp start

    // ======== Phase A2: main chunk partials from y=0 (register-resident) ========
    float bk[CH];
    float ma = 1.0f, mb = 0.0f;
    if (act) {
        float4 x0 = ntv[v0], x1 = ntv[v0 + 1], x2 = ntv[v0 + 2];
        float xs[CH] = {x0.x, x0.y, x0.z, x0.w, x1.x, x1.y, x1.z, x1.w,
                        x2.x, x2.y, x2.z, x2.w};
        float y = 0.0f;
        #pragma unroll
        for (int s = 0; s < CH; ++s) { y = fmaf(OMC, y, CUTOFF * xs[s]); bk[s] = y; }
        mb = y; ma = A12;
    }
    #pragma unroll
    for (int off = 1; off < 32; off <<= 1) {
        float au = __shfl_up_sync(0xffffffffu, ma, off);
        float bu = __shfl_up_sync(0xffffffffu, mb, off);
        if (lane >= off) { mb = fmaf(ma, bu, mb); ma *= au; }
    }
    float a_ie = __shfl_up_sync(0xffffffffu, ma, 1);
    float b_ie = __shfl_up_sync(0xffffffffu, mb, 1);
    if (lane == 0) { a_ie = 1.0f; b_ie = 0.0f; }
    const float y_in = fmaf(a_ie, y_warp, b_ie);

    // ======== Phase A3: transient via sine/exp recurrences (tr kept in regs) ====
    float tr[CH];
    if (act) {
        const float t0 = (float)s0 * TSTEP;
        const float wf = 6.2831853f * freq_t;
        float sn, cs;
        sincosf(wf * t0, &sn, &cs);                 // accurate start phase
        const float sd = __sinf(wf * TSTEP);        // tiny-arg step rotation
        const float cd = __cosf(wf * TSTEP);
        float e1 = __expf(-decay_t * t0);
        float e2 = __expf(-20.0f * decay_t * t0);
        const float m1 = __expf(-decay_t * TSTEP);
        const float m2 = __expf(-20.0f * decay_t * TSTEP);
        const float g2  = gain_t * 0.5f;
        const float gts = gain_t * sat;
        float pk = OMC;                              // 0.9^(k+1)
        #pragma unroll
        for (int s = 0; s < CH; ++s) {
            float y  = fmaf(pk, y_in, bk[s]);        // exact filter output
            float sq = tanh_fast(sn * e1 * gts);     // saturated sine
            tr[s] = fmaf(y * e2, g2, sq);            // + noise component
            float sn2 = fmaf(sn, cd,  cs * sd);
            float cs2 = fmaf(cs, cd, -sn * sd);
            sn = sn2; cs = cs2;
            e1 *= m1; e2 *= m2; pk *= OMC;
        }
        float4* tv = (float4*)g_trans;
        tv[v0]     = make_float4(tr[0], tr[1], tr[2],  tr[3]);
        tv[v0 + 1] = make_float4(tr[4], tr[5], tr[6],  tr[7]);
        tv[v0 + 2] = make_float4(tr[8], tr[9], tr[10], tr[11]);
    }

    __threadfence();       // make g_trans visible cluster-wide
    cluster_sync();

    // ======== Phase B: resonator on CTA 0 only ========
    if (blockIdx.x == 0) {
        float* str = sm;                 // trans copy
        // stage trans into smem (coalesced float4)
        {
            const float4* tv = (const float4*)g_trans;
            float4*       sv = (float4*)str;
            #pragma unroll
            for (int j = 0; j < 24; ++j) {
                int i4 = tid + j * NTHR;
                if (i4 < NSAMP / 4) sv[i4] = tv[i4];
            }
        }
        __syncthreads();

        const float D  = 48000.0f / freq_r;
        const int   Di = (int)D;
        const bool fastp = (D >= 1.0f) && ((float)Di == D) && (Di < NSAMP);

        if (fastp) {
            // Integer delay: frac == 0 exactly -> Di independent chains.
            for (int r = tid; r < Di; r += NTHR) {
                float yv = str[r];        // i < D => valid==0 => out = transient
                g_res[r] = yv;
                #pragma unroll 4
                for (int i = r + Di; i < NSAMP; i += Di) {
                    yv = fmaf(feedback, yv, str[i]);
                    g_res[i] = yv;
                }
            }
        } else {
            // Generic fractional delay: wave-synchronous over zeroed smem res.
            float* sre = sm + NSAMP;
            for (int i = tid; i < NSAMP; i += NTHR) sre[i] = 0.0f;
            __syncthreads();
            if (tid == 0) sre[0] = str[0];
            int cD = (int)ceilf(D);
            int W  = min(max(cD - 1, 1), NTHR);
            __syncthreads();
            for (int b0 = 1; b0 < NSAMP; b0 += W) {
                const int i = b0 + tid;
                if (tid < W && i < NSAMP) {
                    float delayed = (float)i - D;
                    float valid   = (delayed >= 0.0f) ? 1.0f : 0.0f;
                    int fl = min(max((int)floorf(delayed), 0), NSAMP - 1);
                    int ce = min(fl + 1, NSAMP - 1);
                    float frac = delayed - (float)fl;   // after clamp, as in reference
                    float interp = (1.0f - frac) * sre[fl] + frac * sre[ce];
                    sre[i] = str[i] + feedback * interp * valid;
                }
                __syncthreads();
            }
            for (int i = tid; i < NSAMP; i += NTHR) g_res[i] = sre[i];
        }
        __threadfence();   // make g_res visible cluster-wide
    }
    cluster_sync();

    // ======== Phase C: noise envelope + final sum (tr still in registers) ====
    if (act) {
        const float t0 = (float)s0 * TSTEP;
        float eA = __expf(-attack_n * t0);
        float eD = __expf(-decay_n  * t0);
        const float a1 = __expf(-attack_n * TSTEP);
        const float d1 = __expf(-decay_n  * TSTEP);

        const float4* nnv = (const float4*)noise_n;
        const float4* rv  = (const float4*)g_res;
        float4 nn[3] = {nnv[v0], nnv[v0 + 1], nnv[v0 + 2]};
        float4 rs[3] = {rv[v0],  rv[v0 + 1],  rv[v0 + 2]};
        const float* nnf = (const float*)nn;
        const float* rsf = (const float*)rs;

        float o[CH];
        #pragma unroll
        for (int s = 0; s < CH; ++s) {
            float env = (1.0f - eA) * eD;
            o[s] = fmaf(nnf[s] * gain_n, env, fmaf(rsf[s], gain_r, tr[s]));
            eA *= a1; eD *= d1;
        }
        float4* ov = (float4*)out;
        ov[v0]     = make_float4(o[0], o[1], o[2],  o[3]);
        ov[v0 + 1] = make_float4(o[4], o[5], o[6],  o[7]);
        ov[v0 + 2] = make_float4(o[8], o[9], o[10], o[11]);
    }
}

extern "C" void kernel_launch(void* const* d_in, const int* in_sizes, int n_in,
                              void* d_out, int out_size)
{
    const float* params  = (const float*)d_in[0];
    const float* noise_t = (const float*)d_in[1];
    const float* noise_n = (const float*)d_in[2];
    float* out = (float*)d_out;

    const size_t smem_bytes = 2u * NSAMP * sizeof(float);   // 192000 B
    cudaFuncSetAttribute(drum_synth_cluster,
                         cudaFuncAttributeMaxDynamicSharedMemorySize,
                         (int)smem_bytes);

    drum_synth_cluster<<<NCTA, NTHR, smem_bytes>>>(params, noise_t, noise_n, out);
}